// round 6
// baseline (speedup 1.0000x reference)
#include <cuda_runtime.h>
#include <cuda_bf16.h>

// MiscTypeChecker: [B=8192, S=8192] int32 tokens in [0,8), scalar f32 output.
// Backward suffix scan per row with early exit (presence monotone; backward
// first-hit of '1' == last occurrence). Expected read ~4.3MB of 256MB.
//
// Single fused kernel. Tail: relaxed partial-add + RELEASE-only counter per
// block; ONE acquire load in the last block. (R4 lesson: gpu-scope
// fence/acquire emits CCTL.IVALL L1-flush on sm_103a; doing that per-block
// cost ~2us. Now exactly one block pays it.)

#define S_DIM 8192
#define TYPE_RANGE 8

__device__ float    g_partial = 0.0f;
__device__ unsigned g_done    = 0u;

__device__ __forceinline__ void red_add_relaxed_f32(float* p, float v) {
    asm volatile("red.relaxed.gpu.global.add.f32 [%0], %1;"
                 :: "l"(p), "f"(v) : "memory");
}
__device__ __forceinline__ unsigned atom_inc_release(unsigned* p) {
    unsigned old;
    asm volatile("atom.release.gpu.global.add.u32 %0, [%1], 1;"
                 : "=r"(old) : "l"(p) : "memory");
    return old;
}
__device__ __forceinline__ float ld_acquire_f32(const float* p) {
    float v;
    asm volatile("ld.acquire.gpu.global.f32 %0, [%1];"
                 : "=f"(v) : "l"(p) : "memory");
    return v;
}

__device__ __forceinline__ void chunk_stats(const int* __restrict__ rp,
                                            int base, int lane,
                                            unsigned& p_out, int& l_out) {
    const int4 v = reinterpret_cast<const int4*>(rp + base)[lane];
    const int eb = base + lane * 4;
    // presence (reference clips to [0, TYPE_RANGE-1])
    const int cx = min(max(v.x, 0), TYPE_RANGE - 1);
    const int cy = min(max(v.y, 0), TYPE_RANGE - 1);
    const int cz = min(max(v.z, 0), TYPE_RANGE - 1);
    const int cw = min(max(v.w, 0), TYPE_RANGE - 1);
    p_out = (1u << cx) | (1u << cy) | (1u << cz) | (1u << cw);
    // highest position of token==1 in this thread's 4 elems
    int l = -1;
    if (v.x == 1) l = eb;
    if (v.y == 1) l = eb + 1;
    if (v.z == 1) l = eb + 2;
    if (v.w == 1) l = eb + 3;
    l_out = l;
}

__global__ void __launch_bounds__(256, 1)
mtc_fused_kernel(const int* __restrict__ mpt, float* __restrict__ out,
                 int B, int nblocks, int out_size) {
    __shared__ int bsum;
    if (threadIdx.x == 0) bsum = 0;

    // Defensive: zero any extra output elements (block 0 only; usually none).
    if (blockIdx.x == 0) {
        for (int i = 1 + (int)threadIdx.x; i < out_size; i += (int)blockDim.x)
            out[i] = 0.0f;
    }
    __syncthreads();

    const int warp = threadIdx.x >> 5;
    const int lane = threadIdx.x & 31;
    const int row  = blockIdx.x * 8 + warp;

    if (row < B) {
        const int* __restrict__ rp = mpt + (long long)row * S_DIM;

        // Head load (rg1/rg2) issued up front: overlaps the chunk DRAM trip.
        int h0 = 0, h1 = 1;
        if (lane == 0) {
            const int2 h = *reinterpret_cast<const int2*>(rp);
            h0 = h.x; h1 = h.y;
        }

        // Peeled first chunk (last 128 elems): terminates the scan for
        // essentially every row (P(fallback) ~ 4e-8 for uniform data).
        unsigned p; int l;
        chunk_stats(rp, S_DIM - 128, lane, p, l);
        unsigned pres = __reduce_or_sync(0xffffffffu, p);
        int last1 = __reduce_max_sync(0xffffffffu, l);

        if (!(pres == 0xFFu && last1 >= 0)) {
            for (int base = S_DIM - 256; base >= 0; base -= 128) {
                chunk_stats(rp, base, lane, p, l);
                pres |= __reduce_or_sync(0xffffffffu, p);
                if (last1 < 0)
                    last1 = __reduce_max_sync(0xffffffffu, l);
                if (pres == 0xFFu && last1 >= 0) break;  // warp-uniform
            }
        }

        if (lane == 0) {
            int r = ((h0 != 0) + (h1 != 1)) * 4;

            const int miss = TYPE_RANGE - __popc(pres);
            r += miss * miss;

            int rg4 = 6;
            if (last1 > 0 && last1 < S_DIM - 5) {
                // Lines just fetched by this warp -> L1 hits.
                rg4 = (rp[last1 + 1] != 2) + (rp[last1 + 2] != 4) +
                      (rp[last1 + 3] != 5) + (rp[last1 + 4] != 6) +
                      (rp[last1 + 5] != 3);
            }
            atomicAdd(&bsum, r + rg4);
        }
    }

    __syncthreads();

    if (threadIdx.x == 0) {
        // Float accumulation is exact: integer-valued, total < 2^24.
        red_add_relaxed_f32(&g_partial, (float)bsum);
        // Release orders the partial-add before this counter increment
        // (release sequence): cheap, no L1 invalidate.
        const unsigned prev = atom_inc_release(&g_done);
        if (prev == (unsigned)nblocks - 1u) {
            // Single acquire in the whole grid: sees all released partials.
            out[0] = ld_acquire_f32(&g_partial);
            // Reset for next graph replay (no concurrent writers remain;
            // kernel boundary orders this vs. the next launch).
            g_partial = 0.0f;
            g_done = 0u;
        }
    }
}

extern "C" void kernel_launch(void* const* d_in, const int* in_sizes, int n_in,
                              void* d_out, int out_size) {
    // Token matrix = largest input (type_range may arrive as a scalar input).
    int big = 0;
    for (int i = 1; i < n_in; i++)
        if (in_sizes[i] > in_sizes[big]) big = i;

    const int* mpt = (const int*)d_in[big];
    float* out = (float*)d_out;
    const int B = in_sizes[big] / S_DIM;
    const int nblocks = (B + 7) / 8;

    mtc_fused_kernel<<<nblocks, 256>>>(mpt, out, B, nblocks, out_size);
}

// round 8
// speedup vs baseline: 1.0258x; 1.0258x over previous
#include <cuda_runtime.h>
#include <cuda_bf16.h>

// MiscTypeChecker: [B=8192, S=8192] int32 tokens in [0,8), scalar f32 output.
// Backward suffix scan per row with early exit (presence monotone; backward
// first-hit of '1' == last occurrence). Expected read ~4.5MB of 256MB.
//
// R7: 4 rows per warp, all chunk+head loads issued up front (MLP~5 per warp)
// so one DRAM latency covers 4 rows. 256-block grid = single resident wave.

#define S_DIM 8192
#define TYPE_RANGE 8
#define RPW 4          // rows per warp
#define WPB 8          // warps per block (256 threads)

__device__ float    g_partial = 0.0f;
__device__ unsigned g_done    = 0u;

__device__ __forceinline__ void red_add_relaxed_f32(float* p, float v) {
    asm volatile("red.relaxed.gpu.global.add.f32 [%0], %1;"
                 :: "l"(p), "f"(v) : "memory");
}
__device__ __forceinline__ unsigned atom_inc_release(unsigned* p) {
    unsigned old;
    asm volatile("atom.release.gpu.global.add.u32 %0, [%1], 1;"
                 : "=r"(old) : "l"(p) : "memory");
    return old;
}
__device__ __forceinline__ float ld_acquire_f32(const float* p) {
    float v;
    asm volatile("ld.acquire.gpu.global.f32 %0, [%1];"
                 : "=f"(v) : "l"(p) : "memory");
    return v;
}

__device__ __forceinline__ void stats4(const int4 v, int eb,
                                       unsigned& p_out, int& l_out) {
    // presence (reference clips to [0, TYPE_RANGE-1])
    const int cx = min(max(v.x, 0), TYPE_RANGE - 1);
    const int cy = min(max(v.y, 0), TYPE_RANGE - 1);
    const int cz = min(max(v.z, 0), TYPE_RANGE - 1);
    const int cw = min(max(v.w, 0), TYPE_RANGE - 1);
    p_out = (1u << cx) | (1u << cy) | (1u << cz) | (1u << cw);
    // highest position of token==1 in this thread's 4 elems
    int l = -1;
    if (v.x == 1) l = eb;
    if (v.y == 1) l = eb + 1;
    if (v.z == 1) l = eb + 2;
    if (v.w == 1) l = eb + 3;
    l_out = l;
}

__global__ void __launch_bounds__(256)
mtc_fused_kernel(const int* __restrict__ mpt, float* __restrict__ out,
                 int B, int nblocks, int out_size) {
    __shared__ int bsum;
    if (threadIdx.x == 0) bsum = 0;
    if (blockIdx.x == 0) {          // defensive: zero any extra out elems
        for (int i = 1 + (int)threadIdx.x; i < out_size; i += (int)blockDim.x)
            out[i] = 0.0f;
    }
    __syncthreads();

    const int warp = threadIdx.x >> 5;
    const int lane = threadIdx.x & 31;
    const int row0 = (blockIdx.x * WPB + warp) * RPW;

    int result = 0;  // lane r (< RPW) accumulates row r's score

    if (row0 < B) {
        // ---- issue ALL loads up front: 4 chunk LDG.128 + heads (MLP) ----
        const int* rp[RPW];
        int4 v[RPW];
        bool valid[RPW];
#pragma unroll
        for (int r = 0; r < RPW; r++) {
            const int row = row0 + r;
            valid[r] = (row < B);
            rp[r] = mpt + (long long)(valid[r] ? row : 0) * S_DIM;
            if (valid[r])
                v[r] = reinterpret_cast<const int4*>(rp[r] + S_DIM - 128)[lane];
        }
        // lane r loads row r's first two tokens (independent, overlaps above)
        int2 h = make_int2(0, 1);
        if (lane < RPW && (row0 + lane) < B)
            h = *reinterpret_cast<const int2*>(mpt + (long long)(row0 + lane) * S_DIM);

        // ---- process rows; loads already in flight / landed ----
#pragma unroll
        for (int r = 0; r < RPW; r++) {
            if (!valid[r]) break;   // warp-uniform

            unsigned p; int l;
            stats4(v[r], (S_DIM - 128) + lane * 4, p, l);
            unsigned pres = __reduce_or_sync(0xffffffffu, p);
            int last1 = __reduce_max_sync(0xffffffffu, l);

            if (!(pres == 0xFFu && last1 >= 0)) {
                // exact fallback: continue backward over the whole row
                for (int base = S_DIM - 256; base >= 0; base -= 128) {
                    const int4 w = reinterpret_cast<const int4*>(rp[r] + base)[lane];
                    unsigned p2; int l2;
                    stats4(w, base + lane * 4, p2, l2);
                    pres |= __reduce_or_sync(0xffffffffu, p2);
                    if (last1 < 0)
                        last1 = __reduce_max_sync(0xffffffffu, l2);
                    if (pres == 0xFFu && last1 >= 0) break;
                }
            }

            if (lane == r) {
                int rr = ((h.x != 0) + (h.y != 1)) * 4;
                const int miss = TYPE_RANGE - __popc(pres);
                rr += miss * miss;
                int rg4 = 6;
                if (last1 > 0 && last1 < S_DIM - 5) {
                    const int* q = rp[r] + last1;   // lines just fetched: L1 hits
                    rg4 = (q[1] != 2) + (q[2] != 4) + (q[3] != 5) +
                          (q[4] != 6) + (q[5] != 3);
                }
                result += rr + rg4;
            }
        }

        const int wsum = __reduce_add_sync(0xffffffffu, result);
        if (lane == 0 && wsum != 0) atomicAdd(&bsum, wsum);
    }

    __syncthreads();

    if (threadIdx.x == 0) {
        // Float accumulation exact: integer-valued, total < 2^24.
        red_add_relaxed_f32(&g_partial, (float)bsum);
        const unsigned prev = atom_inc_release(&g_done);
        if (prev == (unsigned)nblocks - 1u) {
            out[0] = ld_acquire_f32(&g_partial);   // single acquire chip-wide
            g_partial = 0.0f;                      // reset for next replay
            g_done = 0u;
        }
    }
}

extern "C" void kernel_launch(void* const* d_in, const int* in_sizes, int n_in,
                              void* d_out, int out_size) {
    // Token matrix = largest input (type_range may arrive as a scalar input).
    int big = 0;
    for (int i = 1; i < n_in; i++)
        if (in_sizes[i] > in_sizes[big]) big = i;

    const int* mpt = (const int*)d_in[big];
    float* out = (float*)d_out;
    const int B = in_sizes[big] / S_DIM;
    const int nblocks = (B + RPW * WPB - 1) / (RPW * WPB);   // 256 for B=8192

    mtc_fused_kernel<<<nblocks, 256>>>(mpt, out, B, nblocks, out_size);
}